// round 9
// baseline (speedup 1.0000x reference)
#include <cuda_runtime.h>

// ---------------- problem constants ----------------
#define N_NODES 10000
#define N_EDGES 30000
#define DIN     64
#define EDIM    16
#define H1      128
#define H2      64
#define NCLS    10
#define G1COLS  (17*64)   // 1088: 16 edge-attr channels + 1 bias channel
#define G2COLS  (17*10)   // 170

// ---------------- scratch (no runtime alloc allowed) ----------------
__device__ float g_h1   [N_NODES*H1];
__device__ float g_Wbig1[H1*G1COLS];
__device__ float g_G1   [N_NODES*G1COLS];
__device__ float g_agg1 [N_NODES*H2];
__device__ float g_h2   [N_NODES*H2];
__device__ float g_Wbig2[H2*G2COLS];
__device__ float g_G2   [N_NODES*G2COLS];
__device__ float g_z    [N_NODES*NCLS];
__device__ int   g_idx64;   // 1 if edge_index buffer is int64, 0 if int32

// ---------------- packed f32x2 helpers (sm_103a) ----------------
__device__ __forceinline__ unsigned long long pack_f32x2(float lo, float hi) {
    unsigned long long r;
    asm("mov.b64 %0, {%1, %2};" : "=l"(r) : "f"(lo), "f"(hi));
    return r;
}
__device__ __forceinline__ void unpack_f32x2(unsigned long long v, float& lo, float& hi) {
    asm("mov.b64 {%0, %1}, %2;" : "=f"(lo), "=f"(hi) : "l"(v));
}
__device__ __forceinline__ void ffma2(unsigned long long& d,
                                      unsigned long long a, unsigned long long b) {
    asm("fma.rn.f32x2 %0, %1, %2, %3;" : "=l"(d) : "l"(a), "l"(b), "l"(d));
}

// ---------------- edge_index dtype detection ----------------
// int64 little-endian: hi word of every value is 0 (indices in [0,10000)).
// int32: odd-position words are random indices; 256 all-zero is impossible.
__global__ void detect_idx_kernel(const unsigned int* __restrict__ w) {
    __shared__ int nz;
    if (threadIdx.x == 0) nz = 0;
    __syncthreads();
    if (w[2 * threadIdx.x + 1] != 0u) atomicAdd(&nz, 1);
    __syncthreads();
    if (threadIdx.x == 0) g_idx64 = (nz == 0) ? 1 : 0;
}

__device__ __forceinline__ void load_edge(const void* __restrict__ ei, int e,
                                          int& s, int& d) {
    if (g_idx64) {
        const long long* p = (const long long*)ei;
        s = (int)p[e];
        d = (int)p[N_EDGES + e];
    } else {
        const int* p = (const int*)ei;
        s = p[e];
        d = p[N_EDGES + e];
    }
}

// ---------------- weight rearrangement + zero init (fused) ----------------
__global__ void prep_and_zero(const float* __restrict__ We1, const float* __restrict__ be1,
                              const float* __restrict__ We2, const float* __restrict__ be2) {
    int idx = blockIdx.x * blockDim.x + threadIdx.x;
    const int n1 = H1 * G1COLS;              // 139264
    const int n2 = H2 * G2COLS;              // 10880
    const int n3 = N_NODES * H2;             // 640000
    const int n4 = N_NODES * NCLS;           // 100000
    if (idx < n1) {
        int i = idx / G1COLS, j = idx % G1COLS;
        int k = j >> 6, o = j & 63;
        g_Wbig1[idx] = (k < 16) ? We1[k * (H1 * H2) + i * H2 + o] : be1[i * H2 + o];
    } else if (idx < n1 + n2) {
        int e = idx - n1;
        int i = e / G2COLS, j = e % G2COLS;
        int k = j / 10, c = j % 10;
        g_Wbig2[e] = (k < 16) ? We2[k * (H2 * NCLS) + i * NCLS + c] : be2[i * NCLS + c];
    } else if (idx < n1 + n2 + n3) {
        g_agg1[idx - n1 - n2] = 0.0f;
    } else if (idx < n1 + n2 + n3 + n4) {
        g_z[idx - n1 - n2 - n3] = 0.0f;
    }
}

// ---------------- generic tiled fp32 GEMM ------------------------------------
// f32x2 packed FMA, M-paired accumulators, 2-stage double-buffered pipeline,
// float2-vectorized epilogue stores.
// C[M,N] = epilogue(A[M,K] @ B[K,N])
//   mode 0: C = AB ; mode 1: relu(AB+bias) ; mode 2: relu(AB+bias+extra)
// Tile: 128(M) x 64(N), K-chunks of 16, 256 threads, 8x4 micro-tile.
// K must be a multiple of 16; N must be even (all call sites satisfy both).
#define AS_STRIDE 132   // pad: keeps 16B alignment for float4 a-frag loads
__global__ void __launch_bounds__(256)
gemm_tiled(const float* __restrict__ A, const float* __restrict__ B,
           float* __restrict__ C, int M, int N, int K,
           int mode, const float* __restrict__ bias,
           const float* __restrict__ extra) {
    __shared__ float As[2][16 * AS_STRIDE];   // [buf][kk][m]
    __shared__ float Bs[2][16 * 64];          // [buf][kk][n]

    const int tid = threadIdx.x;
    const int tx = tid & 15;         // -> 4 N-columns
    const int ty = tid >> 4;         // -> 8 M-rows (4 pairs)
    const int mBase = blockIdx.x * 128;
    const int nBase = blockIdx.y * 64;

    unsigned long long acc[4][4];
#pragma unroll
    for (int i = 0; i < 4; i++)
#pragma unroll
        for (int j = 0; j < 4; j++) acc[i][j] = 0ull;

    float aReg[8], bReg[4];
    const int nChunks = K >> 4;

    // ---- stage chunk 0 ----
#pragma unroll
    for (int l = 0; l < 8; l++) {
        int s = tid + 256 * l;
        int row = s >> 4, kk = s & 15;
        int gm = mBase + row;
        aReg[l] = (gm < M) ? A[(long long)gm * K + kk] : 0.0f;
    }
#pragma unroll
    for (int l = 0; l < 4; l++) {
        int s = tid + 256 * l;
        int kk = s >> 6, n = s & 63;
        int gn = nBase + n;
        bReg[l] = (gn < N) ? B[(long long)kk * N + gn] : 0.0f;
    }
#pragma unroll
    for (int l = 0; l < 8; l++) {
        int s = tid + 256 * l;
        As[0][(s & 15) * AS_STRIDE + (s >> 4)] = aReg[l];
    }
#pragma unroll
    for (int l = 0; l < 4; l++) {
        int s = tid + 256 * l;
        Bs[0][s] = bReg[l];
    }
    __syncthreads();

    for (int c = 0; c < nChunks; ++c) {
        const int cur = c & 1;
        const bool more = (c + 1) < nChunks;

        // ---- issue LDGs for chunk c+1 (overlaps with compute below) ----
        if (more) {
            int k0 = (c + 1) << 4;
#pragma unroll
            for (int l = 0; l < 8; l++) {
                int s = tid + 256 * l;
                int row = s >> 4, kk = s & 15;
                int gm = mBase + row;
                aReg[l] = (gm < M) ? A[(long long)gm * K + k0 + kk] : 0.0f;
            }
#pragma unroll
            for (int l = 0; l < 4; l++) {
                int s = tid + 256 * l;
                int kk = s >> 6, n = s & 63;
                int gn = nBase + n;
                bReg[l] = (gn < N) ? B[(long long)(k0 + kk) * N + gn] : 0.0f;
            }
        }

        // ---- compute on buffer cur ----
#pragma unroll
        for (int kk = 0; kk < 16; ++kk) {
            float4 a0 = *(const float4*)&As[cur][kk * AS_STRIDE + ty * 8];
            float4 a1 = *(const float4*)&As[cur][kk * AS_STRIDE + ty * 8 + 4];
            float4 b4 = *(const float4*)&Bs[cur][kk * 64 + tx * 4];
            unsigned long long ap[4] = {
                pack_f32x2(a0.x, a0.y), pack_f32x2(a0.z, a0.w),
                pack_f32x2(a1.x, a1.y), pack_f32x2(a1.z, a1.w)
            };
            unsigned long long bd[4] = {
                pack_f32x2(b4.x, b4.x), pack_f32x2(b4.y, b4.y),
                pack_f32x2(b4.z, b4.z), pack_f32x2(b4.w, b4.w)
            };
#pragma unroll
            for (int i = 0; i < 4; i++)
#pragma unroll
                for (int j = 0; j < 4; j++) ffma2(acc[i][j], ap[i], bd[j]);
        }

        // ---- stage chunk c+1 into alternate buffer ----
        if (more) {
            const int nxt = cur ^ 1;
#pragma unroll
            for (int l = 0; l < 8; l++) {
                int s = tid + 256 * l;
                As[nxt][(s & 15) * AS_STRIDE + (s >> 4)] = aReg[l];
            }
#pragma unroll
            for (int l = 0; l < 4; l++) {
                int s = tid + 256 * l;
                Bs[nxt][s] = bReg[l];
            }
            __syncthreads();
        }
    }

    // epilogue: unpack M-pairs, store as float2 pairs over N (N even; 8B aligned)
    const int nCol = nBase + tx * 4;
#pragma unroll
    for (int i = 0; i < 4; i++) {
        float v[2][4];   // [h][j]
#pragma unroll
        for (int j = 0; j < 4; j++)
            unpack_f32x2(acc[i][j], v[0][j], v[1][j]);
#pragma unroll
        for (int h = 0; h < 2; h++) {
            int m = mBase + ty * 8 + i * 2 + h;
            if (m >= M) continue;
#pragma unroll
            for (int jp = 0; jp < 2; jp++) {          // column pairs (0,1), (2,3)
                int n = nCol + jp * 2;
                if (n >= N) continue;
                float w0 = v[h][jp * 2], w1 = v[h][jp * 2 + 1];
                if (mode >= 1) { w0 += bias[n]; if (n + 1 < N) w1 += bias[n + 1]; }
                if (mode == 2) {
                    w0 += extra[(long long)m * N + n];
                    if (n + 1 < N) w1 += extra[(long long)m * N + n + 1];
                }
                if (mode >= 1) { w0 = fmaxf(w0, 0.0f); w1 = fmaxf(w1, 0.0f); }
                if (n + 1 < N) {
                    *(float2*)&C[(long long)m * N + n] = make_float2(w0, w1);
                } else {
                    C[(long long)m * N + n] = w0;
                }
            }
        }
    }
}

// ---------------- edge combine, layer 1 ----------------
// agg1[dst, o] += sum_k ea[e,k] * G1[src, k*64+o] + G1[src, 1024+o]
// one warp per edge; lane covers o = 2*lane, 2*lane+1 (contiguous -> LDG.64)
__global__ void edge_combine1(const float* __restrict__ ea,
                              const void* __restrict__ ei) {
    int warp = (blockIdx.x * blockDim.x + threadIdx.x) >> 5;
    int lane = threadIdx.x & 31;
    if (warp >= N_EDGES) return;
    int s, d;
    load_edge(ei, warp, s, d);
    const float* __restrict__ G = g_G1 + (long long)s * G1COLS;
    float av = (lane < 16) ? ea[warp * EDIM + lane] : 0.0f;
    float2 bias2v = *(const float2*)&G[1024 + 2 * lane];
    float acc0 = bias2v.x, acc1 = bias2v.y;
#pragma unroll
    for (int k = 0; k < 16; ++k) {
        float a = __shfl_sync(0xffffffffu, av, k);
        float2 g2 = *(const float2*)&G[k * 64 + 2 * lane];
        acc0 += a * g2.x;
        acc1 += a * g2.y;
    }
    atomicAdd(&g_agg1[(long long)d * H2 + 2 * lane],     acc0);
    atomicAdd(&g_agg1[(long long)d * H2 + 2 * lane + 1], acc1);
}

// ---------------- edge combine, layer 2 ----------------
// z[dst, c..c+1] += sum_k ea[e,k] * G2[src, k*10+c..c+1] + G2[src, 160+c..c+1]
// one thread per (edge, class-pair): 5 threads/edge, 2 classes each.
__global__ void edge_combine2(const float* __restrict__ ea,
                              const void* __restrict__ ei) {
    int t = blockIdx.x * blockDim.x + threadIdx.x;
    if (t >= N_EDGES * (NCLS / 2)) return;
    int e = t / (NCLS / 2);
    int c = (t % (NCLS / 2)) * 2;
    int s, d;
    load_edge(ei, e, s, d);
    const float* __restrict__ G = g_G2 + (long long)s * G2COLS;
    float2 b2 = *(const float2*)&G[160 + c];
    float acc0 = b2.x, acc1 = b2.y;
#pragma unroll
    for (int k = 0; k < 16; ++k) {
        float a = ea[e * EDIM + k];
        float2 g2 = *(const float2*)&G[k * NCLS + c];
        acc0 += a * g2.x;
        acc1 += a * g2.y;
    }
    atomicAdd(&g_z[(long long)d * NCLS + c],     acc0);
    atomicAdd(&g_z[(long long)d * NCLS + c + 1], acc1);
}

// ---------------- final: z + h2@root2 + bias2 -> log_softmax ----------------
// one warp per node
__global__ void final_logsoftmax(const float* __restrict__ root2,
                                 const float* __restrict__ bias2,
                                 float* __restrict__ out) {
    int node = (blockIdx.x * blockDim.x + threadIdx.x) >> 5;
    int lane = threadIdx.x & 31;
    if (node >= N_NODES) return;
    const float* __restrict__ h = g_h2 + node * H2;
    float h0 = h[lane];
    float h1v = h[32 + lane];
    bool act = lane < NCLS;
    float acc = 0.0f;
#pragma unroll
    for (int i = 0; i < 64; ++i) {
        float hv = __shfl_sync(0xffffffffu, (i < 32) ? h0 : h1v, i & 31);
        if (act) acc += hv * root2[i * NCLS + lane];
    }
    float zf = act ? (g_z[node * NCLS + lane] + bias2[lane] + acc) : -1e30f;
    // reductions stay within 16-lane groups (offsets <= 8); lanes 0..15 carry the data
    float mx = zf;
#pragma unroll
    for (int off = 8; off; off >>= 1)
        mx = fmaxf(mx, __shfl_xor_sync(0xffffffffu, mx, off));
    float ex = act ? expf(zf - mx) : 0.0f;
    float ssum = ex;
#pragma unroll
    for (int off = 8; off; off >>= 1)
        ssum += __shfl_xor_sync(0xffffffffu, ssum, off);
    if (act) out[node * NCLS + lane] = zf - mx - logf(ssum);
}

// ---------------- launch ----------------
extern "C" void kernel_launch(void* const* d_in, const int* in_sizes, int n_in,
                              void* d_out, int out_size) {
    const float* x     = (const float*)d_in[0];
    const float* ea    = (const float*)d_in[1];
    const void*  ei    = d_in[2];                 // int32 or int64; auto-detected
    const float* W1    = (const float*)d_in[3];
    const float* b1    = (const float*)d_in[4];
    const float* We1   = (const float*)d_in[5];
    const float* be1   = (const float*)d_in[6];
    const float* root1 = (const float*)d_in[7];
    const float* bias1 = (const float*)d_in[8];
    const float* We2   = (const float*)d_in[9];
    const float* be2   = (const float*)d_in[10];
    const float* root2 = (const float*)d_in[11];
    const float* bias2 = (const float*)d_in[12];
    float* out = (float*)d_out;

    float *h1p, *Wb1p, *G1p, *agg1p, *h2p, *Wb2p, *G2p;
    cudaGetSymbolAddress((void**)&h1p,   g_h1);
    cudaGetSymbolAddress((void**)&Wb1p,  g_Wbig1);
    cudaGetSymbolAddress((void**)&G1p,   g_G1);
    cudaGetSymbolAddress((void**)&agg1p, g_agg1);
    cudaGetSymbolAddress((void**)&h2p,   g_h2);
    cudaGetSymbolAddress((void**)&Wb2p,  g_Wbig2);
    cudaGetSymbolAddress((void**)&G2p,   g_G2);

    detect_idx_kernel<<<1, 256>>>((const unsigned int*)ei);

    const int prepN = H1 * G1COLS + H2 * G2COLS + N_NODES * H2 + N_NODES * NCLS;
    prep_and_zero<<<(prepN + 255) / 256, 256>>>(We1, be1, We2, be2);

    const int mTiles = (N_NODES + 127) / 128;  // 79
    // h1 = relu(x @ W1 + b1)            [10000,64]@[64,128]
    gemm_tiled<<<dim3(mTiles, (H1 + 63) / 64), 256>>>(
        x, W1, h1p, N_NODES, H1, DIN, 1, b1, nullptr);
    // G1 = h1 @ Wbig1                   [10000,128]@[128,1088]
    gemm_tiled<<<dim3(mTiles, G1COLS / 64), 256>>>(
        h1p, Wb1p, G1p, N_NODES, G1COLS, H1, 0, nullptr, nullptr);
    // per-edge combine + scatter into agg1
    edge_combine1<<<N_EDGES / 8, 256>>>(ea, ei);
    // h2 = relu(agg1 + h1 @ root1 + bias1)   [10000,128]@[128,64]
    gemm_tiled<<<dim3(mTiles, 1), 256>>>(
        h1p, root1, h2p, N_NODES, H2, H1, 2, bias1, agg1p);
    // G2 = h2 @ Wbig2                   [10000,64]@[64,170]
    gemm_tiled<<<dim3(mTiles, (G2COLS + 63) / 64), 256>>>(
        h2p, Wb2p, G2p, N_NODES, G2COLS, H2, 0, nullptr, nullptr);
    // per-edge combine + scatter into z
    edge_combine2<<<(N_EDGES * (NCLS / 2) + 255) / 256, 256>>>(ea, ei);
    // out = log_softmax(z + h2 @ root2 + bias2)
    final_logsoftmax<<<(N_NODES + 7) / 8, 256>>>(root2, bias2, out);
}